// round 10
// baseline (speedup 1.0000x reference)
#include <cuda_runtime.h>
#include <cuda_fp16.h>
#include <mma.h>
#include <cstdint>

using namespace nvcuda;

// ---------------------------------------------------------------------------
// Problem constants
// ---------------------------------------------------------------------------
#define M_TOK   4096
#define K_IN    4096
#define N_OUT   11008
#define GROUPSZ 128

// GEMM tiling: warp-specialized, 4 MMA warps (64x64) + 4 producer warps
#define BM      128
#define BN      128
#define BK      64
#define NITER   (K_IN / BK)        // 64
#define NTHREADS 256
#define NSTAGE  3

#define A_LD    72                 // 64 + 8 pad (halves)
#define B_LD    136                // 128 + 8 pad (halves)
#define C_LD    68                 // 64 + 4 pad (floats), epilogue staging

#define A_STAGE_BYTES (BM * A_LD * 2)      // 18432
#define B_STAGE_BYTES (BK * B_LD * 2)      // 17408
#define STAGE_BYTES   (A_STAGE_BYTES + B_STAGE_BYTES)   // 35840
#define SMEM_DYN      (NSTAGE * STAGE_BYTES)            // 107520

// named barriers: full[s] = 1+s, empty[s] = 4+s  (id 0 left for syncthreads)
#define BAR_FULL(s)  (1 + (s))
#define BAR_EMPTY(s) (4 + (s))

// fp16 x scratch (no allocations allowed)
__device__ __half g_Xh[(size_t)M_TOK * K_IN];

// ---------------------------------------------------------------------------
// Kernel 0: convert x f32 -> f16 (harness materializes jax f16 as f32)
// ---------------------------------------------------------------------------
__global__ void convert_x_kernel(const float* __restrict__ x)
{
    size_t i = ((size_t)blockIdx.x * blockDim.x + threadIdx.x) * 4;
    if (i >= (size_t)M_TOK * K_IN) return;
    float4 v = *(const float4*)(x + i);
    *(__half2*)(g_Xh + i)     = __floats2half2_rn(v.x, v.y);
    *(__half2*)(g_Xh + i + 2) = __floats2half2_rn(v.z, v.w);
}

// ---------------------------------------------------------------------------
// helpers
// ---------------------------------------------------------------------------
__device__ __forceinline__ uint32_t smem_u32(const void* p) {
    uint32_t a;
    asm("{ .reg .u64 t; cvta.to.shared.u64 t, %1; cvt.u32.u64 %0, t; }"
        : "=r"(a) : "l"(p));
    return a;
}
__device__ __forceinline__ void cp_async16(uint32_t saddr, const void* gaddr) {
    asm volatile("cp.async.ca.shared.global [%0], [%1], 16;\n"
                 :: "r"(saddr), "l"(gaddr));
}
#define CP_COMMIT()  asm volatile("cp.async.commit_group;\n" ::: "memory")
#define CP_WAIT0()   asm volatile("cp.async.wait_group 0;\n" ::: "memory")
#define BAR_SYNC(id, cnt) \
    asm volatile("bar.sync %0, %1;" :: "r"(id), "r"(cnt) : "memory")
#define BAR_ARRIVE(id, cnt) \
    asm volatile("bar.arrive %0, %1;" :: "r"(id), "r"(cnt) : "memory")

// ---------------------------------------------------------------------------
// Fused 4-bit dequant + HMMA GEMM, warp-specialized:
//   C[M,N] = X[M,K] * dequant(Q)[K,N] + bias
//
// Warps 0-3 (consumers): only fragment loads + wmma, gated by full/empty
//   named barriers -> tensor pipe never idles on loads/dequant.
// Warps 4-7 (producers): A tile via cp.async; B tile = fused GPTQ 4-bit
//   dequant (fp16 magic 0x6400|q, bit-exact) into SMEM; 3-stage ring.
//
// qweight: [K/8, N] int32 nibbles pack K; qzeros: [G, N/8] nibbles pack N;
// scales: [G, N] f32 (fp16 values).
// ---------------------------------------------------------------------------
__global__ void __launch_bounds__(NTHREADS, 1)
gemm_q4_kernel(const int* __restrict__ qweight,
               const int* __restrict__ qzeros,
               const float* __restrict__ scales,
               const float* __restrict__ bias,
               float* __restrict__ out)
{
    extern __shared__ __align__(16) char smem[];
    const uint32_t sbase = smem_u32(smem);

    const int tid  = threadIdx.x;
    const int warp = tid >> 5;
    const int lane = tid & 31;
    const int bm   = blockIdx.x * BM;   // M fastest: A + qweight stay L2-resident
    const int bn   = blockIdx.y * BN;

    if (warp < 4) {
        // =================== CONSUMER: MMA only ===================
        const int wm = (warp >> 1) * 64;
        const int wn = (warp & 1) * 64;

        wmma::fragment<wmma::accumulator, 16, 16, 16, float> acc[4][4];
        #pragma unroll
        for (int i = 0; i < 4; i++)
            #pragma unroll
            for (int j = 0; j < 4; j++)
                wmma::fill_fragment(acc[i][j], 0.0f);

        for (int ks = 0; ks < NITER; ks++) {
            const int buf = ks % NSTAGE;
            BAR_SYNC(BAR_FULL(buf), NTHREADS);

            const __half* As = (const __half*)(smem + buf * STAGE_BYTES);
            const __half* Bs = (const __half*)(smem + buf * STAGE_BYTES + A_STAGE_BYTES);
            #pragma unroll
            for (int kk = 0; kk < BK; kk += 16) {
                wmma::fragment<wmma::matrix_a, 16, 16, 16, __half, wmma::row_major> af[4];
                #pragma unroll
                for (int i = 0; i < 4; i++)
                    wmma::load_matrix_sync(af[i], As + (wm + i * 16) * A_LD + kk, A_LD);
                #pragma unroll
                for (int j = 0; j < 4; j++) {
                    wmma::fragment<wmma::matrix_b, 16, 16, 16, __half, wmma::row_major> bf;
                    wmma::load_matrix_sync(bf, Bs + kk * B_LD + wn + j * 16, B_LD);
                    #pragma unroll
                    for (int i = 0; i < 4; i++)
                        wmma::mma_sync(acc[i][j], af[i], bf, acc[i][j]);
                }
            }
            BAR_ARRIVE(BAR_EMPTY(buf), NTHREADS);
        }

        // ---- epilogue: stage fp32 in buffer-1 region (free after last
        //      full-barrier rendezvous; stage 63 reads buffer 0) ----
        float* fbuf = (float*)(smem + STAGE_BYTES) + warp * 16 * C_LD;
        const float* brow = bias + bn + wn;
        #pragma unroll
        for (int i = 0; i < 4; i++) {
            #pragma unroll
            for (int j = 0; j < 4; j++)
                wmma::store_matrix_sync(fbuf + j * 16, acc[i][j], C_LD, wmma::mem_row_major);
            __syncwarp();
            #pragma unroll
            for (int ii = 0; ii < 8; ii++) {
                int idx4 = lane + 32 * ii;          // 256 float4 = 16x64
                int row  = idx4 >> 4;
                int col  = (idx4 & 15) * 4;
                float4 v = *(float4*)(fbuf + row * C_LD + col);
                float4 b4 = *(const float4*)(brow + col);
                v.x += b4.x; v.y += b4.y; v.z += b4.z; v.w += b4.w;
                *(float4*)(out + (size_t)(bm + wm + i * 16 + row) * N_OUT + bn + wn + col) = v;
            }
            __syncwarp();
        }
    } else {
        // =================== PRODUCER: loads + dequant ===================
        const int ptid = tid - 128;              // 0..127
        const int n0   = (ptid & 15) * 8;        // 0,8,...,120
        const int kp0  = ptid >> 4;              // 0..7
        const int o    = bn + n0;                // multiple of 8

        const __half* Xb = g_Xh + (size_t)bm * K_IN;

        uint4   breg[2];
        __half2 hz[4], hs[4];

        auto ldg_b = [&](int ks) {
            const int* qw = qweight + (size_t)(ks * 8 + kp0) * N_OUT + o;
            breg[0] = *(const uint4*)qw;
            breg[1] = *(const uint4*)(qw + 4);
        };
        auto ldg_consts = [&](int g) {
            uint32_t zw = (uint32_t)qzeros[(size_t)g * (N_OUT / 8) + (o >> 3)];
            #pragma unroll
            for (int k = 0; k < 4; k++) {
                uint32_t z0 = ((zw >> (8 * k))     & 15u) + 1u + 0x6400u;
                uint32_t z1 = ((zw >> (8 * k + 4)) & 15u) + 1u + 0x6400u;
                uint32_t p  = z0 | (z1 << 16);
                hz[k] = *(__half2*)&p;
            }
            float4 s0 = *(const float4*)(scales + (size_t)g * N_OUT + o);
            float4 s1 = *(const float4*)(scales + (size_t)g * N_OUT + o + 4);
            hs[0] = __halves2half2(__float2half_rn(s0.x), __float2half_rn(s0.y));
            hs[1] = __halves2half2(__float2half_rn(s0.z), __float2half_rn(s0.w));
            hs[2] = __halves2half2(__float2half_rn(s1.x), __float2half_rn(s1.y));
            hs[3] = __halves2half2(__float2half_rn(s1.z), __float2half_rn(s1.w));
        };
        auto issue_a = [&](int ks, uint32_t abase) {
            const int k0 = ks * BK;
            #pragma unroll
            for (int i = 0; i < 8; i++) {
                int c = ptid + 128 * i;
                int row = c >> 3, cc = c & 7;
                cp_async16(abase + (uint32_t)(row * A_LD + cc * 8) * 2,
                           Xb + (size_t)row * K_IN + k0 + cc * 8);
            }
        };
        auto store_b = [&](uint32_t bbyte) {
            char* dst = smem + bbyte + (kp0 * 8) * (B_LD * 2) + n0 * 2;
            uint4 wa = breg[0], wb = breg[1];
            #pragma unroll
            for (int j = 0; j < 8; j++) {
                uint32_t u01 = 0x64006400u | ((wa.x >> (4 * j)) & 0xFu)
                                           | (((wa.y >> (4 * j)) & 0xFu) << 16);
                uint32_t u23 = 0x64006400u | ((wa.z >> (4 * j)) & 0xFu)
                                           | (((wa.w >> (4 * j)) & 0xFu) << 16);
                uint32_t u45 = 0x64006400u | ((wb.x >> (4 * j)) & 0xFu)
                                           | (((wb.y >> (4 * j)) & 0xFu) << 16);
                uint32_t u67 = 0x64006400u | ((wb.z >> (4 * j)) & 0xFu)
                                           | (((wb.w >> (4 * j)) & 0xFu) << 16);
                __half2 h01 = __hmul2(__hsub2(*(__half2*)&u01, hz[0]), hs[0]);
                __half2 h23 = __hmul2(__hsub2(*(__half2*)&u23, hz[1]), hs[1]);
                __half2 h45 = __hmul2(__hsub2(*(__half2*)&u45, hz[2]), hs[2]);
                __half2 h67 = __hmul2(__hsub2(*(__half2*)&u67, hz[3]), hs[3]);
                uint4 v = make_uint4(*(uint32_t*)&h01, *(uint32_t*)&h23,
                                     *(uint32_t*)&h45, *(uint32_t*)&h67);
                *(uint4*)(dst + j * (B_LD * 2)) = v;
            }
        };

        ldg_consts(0);
        ldg_b(0);

        for (int ks = 0; ks < NITER; ks++) {
            const int buf = ks % NSTAGE;
            if (ks >= NSTAGE)
                BAR_SYNC(BAR_EMPTY(buf), NTHREADS);

            issue_a(ks, sbase + buf * STAGE_BYTES);
            CP_COMMIT();
            store_b((uint32_t)(buf * STAGE_BYTES + A_STAGE_BYTES));

            if (ks + 1 < NITER) {
                if (ks & 1)
                    ldg_consts((ks + 1) >> 1);   // group changes after odd ks
                ldg_b(ks + 1);
            }
            CP_WAIT0();
            BAR_ARRIVE(BAR_FULL(buf), NTHREADS);
        }
    }
}

// ---------------------------------------------------------------------------
// Launch.  Inputs: x(f32), qweight(i32), qzeros(i32), scales(f32), g_idx(i32),
//                  bias(f32).  Output f32 [M_TOK, N_OUT].
// ---------------------------------------------------------------------------
extern "C" void kernel_launch(void* const* d_in, const int* in_sizes, int n_in,
                              void* d_out, int out_size)
{
    const float* x       = (const float*)d_in[0];
    const int*   qweight = (const int*)d_in[1];
    const int*   qzeros  = (const int*)d_in[2];
    const float* scales  = (const float*)d_in[3];
    const float* bias    = (const float*)d_in[5];
    float* out = (float*)d_out;

    {
        size_t n4 = (size_t)M_TOK * K_IN / 4;
        convert_x_kernel<<<(unsigned)((n4 + 255) / 256), 256>>>(x);
    }
    {
        cudaFuncSetAttribute(gemm_q4_kernel,
                             cudaFuncAttributeMaxDynamicSharedMemorySize,
                             SMEM_DYN);
        dim3 grid(M_TOK / BM, N_OUT / BN);   // (32, 86), M fastest
        gemm_q4_kernel<<<grid, NTHREADS, SMEM_DYN>>>(qweight, qzeros, scales, bias, out);
    }
}

// round 11
// speedup vs baseline: 1.1812x; 1.1812x over previous
#include <cuda_runtime.h>
#include <cuda_fp16.h>
#include <mma.h>
#include <cstdint>

using namespace nvcuda;

// ---------------------------------------------------------------------------
// Problem constants
// ---------------------------------------------------------------------------
#define M_TOK   4096
#define K_IN    4096
#define N_OUT   11008
#define GROUPSZ 128

// GEMM tiling: 4 warps, warp tile 64x64, 2 CTAs/SM, 3-stage ring
#define BM      128
#define BN      128
#define BK      64
#define NITER   (K_IN / BK)        // 64
#define NTHREADS 128               // 4 warps, warp grid 2(M) x 2(N)
#define NSTAGE  3

#define A_LD    72                 // 64 + 8 pad (halves)
#define B_LD    136                // 128 + 8 pad (halves)
#define C_LD    68                 // 64 + 4 pad (floats), epilogue staging

#define A_STAGE_BYTES (BM * A_LD * 2)      // 18432
#define B_STAGE_BYTES (BK * B_LD * 2)      // 17408
#define STAGE_BYTES   (A_STAGE_BYTES + B_STAGE_BYTES)   // 35840
#define SMEM_DYN      (NSTAGE * STAGE_BYTES)            // 107520 (x2 CTAs = 215KB)

// fp16 x scratch (no allocations allowed)
__device__ __half g_Xh[(size_t)M_TOK * K_IN];

// ---------------------------------------------------------------------------
// Kernel 0: convert x f32 -> f16 (harness materializes jax f16 as f32)
// ---------------------------------------------------------------------------
__global__ void convert_x_kernel(const float* __restrict__ x)
{
    size_t i = ((size_t)blockIdx.x * blockDim.x + threadIdx.x) * 4;
    if (i >= (size_t)M_TOK * K_IN) return;
    float4 v = *(const float4*)(x + i);
    *(__half2*)(g_Xh + i)     = __floats2half2_rn(v.x, v.y);
    *(__half2*)(g_Xh + i + 2) = __floats2half2_rn(v.z, v.w);
}

// ---------------------------------------------------------------------------
// helpers
// ---------------------------------------------------------------------------
__device__ __forceinline__ uint32_t smem_u32(const void* p) {
    uint32_t a;
    asm("{ .reg .u64 t; cvta.to.shared.u64 t, %1; cvt.u32.u64 %0, t; }"
        : "=r"(a) : "l"(p));
    return a;
}
__device__ __forceinline__ void cp_async16(uint32_t saddr, const void* gaddr) {
    asm volatile("cp.async.ca.shared.global [%0], [%1], 16;\n"
                 :: "r"(saddr), "l"(gaddr));
}
#define CP_COMMIT() asm volatile("cp.async.commit_group;\n" ::: "memory")
#define CP_WAIT2()  asm volatile("cp.async.wait_group 2;\n" ::: "memory")

// ---------------------------------------------------------------------------
// Fused 4-bit dequant + HMMA GEMM:  C[M,N] = X[M,K] * dequant(Q)[K,N] + bias
//
// qweight: [K/8, N] int32, nibbles pack K; qzeros: [G, N/8] nibbles pack N;
// scales: [G, N] f32 (fp16 values).
// Dequant via fp16 magic numbers: fp16(0x6400|q) = 1024+q exactly, so
// (u - (1024+z)) * s == fp16(scale) * fp16(q - z) bit-exactly.
//
// 3-stage ring, 2-stage lookahead: at iter ks we produce stage ks+2
// (cp.async A + dequant-store B from regs prefetched at ks-1) and compute
// stage ks. One commit per iter + wait_group(2): the awaited group was
// committed two stages ago -> cp.async latency fully covered, the only
// per-stage sync is one __syncthreads for STS visibility/buffer reuse.
// 2 CTAs/SM decorrelate barrier phases.
// ---------------------------------------------------------------------------
__global__ void __launch_bounds__(NTHREADS, 2)
gemm_q4_kernel(const int* __restrict__ qweight,
               const int* __restrict__ qzeros,
               const float* __restrict__ scales,
               const float* __restrict__ bias,
               float* __restrict__ out)
{
    extern __shared__ __align__(16) char smem[];
    const uint32_t sbase = smem_u32(smem);

    const int tid  = threadIdx.x;
    const int warp = tid >> 5;
    const int lane = tid & 31;
    const int bm   = blockIdx.x * BM;   // M fastest: A + qweight stay L2-resident
    const int bn   = blockIdx.y * BN;

    // warp tile: 64x64.  warp grid 2(M) x 2(N)
    const int wm = (warp >> 1) * 64;
    const int wn = (warp & 1) * 64;

    const __half* Xb = g_Xh + (size_t)bm * K_IN;

    // ---- B dequant mapping: 1 kp row x 8 cols per thread ----
    const int n0  = (tid & 15) * 8;          // 0,8,...,120
    const int kp0 = tid >> 4;                // 0..7
    const int o   = bn + n0;                 // multiple of 8: one qzeros word

    wmma::fragment<wmma::accumulator, 16, 16, 16, float> acc[4][4];
    #pragma unroll
    for (int i = 0; i < 4; i++)
        #pragma unroll
        for (int j = 0; j < 4; j++)
            wmma::fill_fragment(acc[i][j], 0.0f);

    uint4   breg[2];          // qweight words: 8 cols of one kp row
    __half2 hz[4];            // (1024+z) pairs for col pairs
    __half2 hs[4];            // scale pairs

    auto ldg_b = [&](int ks) {
        const int* qw = qweight + (size_t)(ks * 8 + kp0) * N_OUT + o;
        breg[0] = *(const uint4*)qw;
        breg[1] = *(const uint4*)(qw + 4);
    };
    auto ldg_consts = [&](int g) {
        uint32_t zw = (uint32_t)qzeros[(size_t)g * (N_OUT / 8) + (o >> 3)];
        #pragma unroll
        for (int k = 0; k < 4; k++) {
            uint32_t z0 = ((zw >> (8 * k))     & 15u) + 1u + 0x6400u;
            uint32_t z1 = ((zw >> (8 * k + 4)) & 15u) + 1u + 0x6400u;
            uint32_t p  = z0 | (z1 << 16);
            hz[k] = *(__half2*)&p;
        }
        float4 s0 = *(const float4*)(scales + (size_t)g * N_OUT + o);
        float4 s1 = *(const float4*)(scales + (size_t)g * N_OUT + o + 4);
        hs[0] = __halves2half2(__float2half_rn(s0.x), __float2half_rn(s0.y));
        hs[1] = __halves2half2(__float2half_rn(s0.z), __float2half_rn(s0.w));
        hs[2] = __halves2half2(__float2half_rn(s1.x), __float2half_rn(s1.y));
        hs[3] = __halves2half2(__float2half_rn(s1.z), __float2half_rn(s1.w));
    };
    auto issue_a = [&](int ks, uint32_t abase) {
        const int k0 = ks * BK;
        #pragma unroll
        for (int i = 0; i < 8; i++) {
            int c = tid + NTHREADS * i;
            int row = c >> 3, cc = c & 7;
            cp_async16(abase + (uint32_t)(row * A_LD + cc * 8) * 2,
                       Xb + (size_t)row * K_IN + k0 + cc * 8);
        }
    };
    auto store_b = [&](uint32_t bbyte) {
        char* dst = smem + bbyte + (kp0 * 8) * (B_LD * 2) + n0 * 2;
        uint4 wa = breg[0], wb = breg[1];
        #pragma unroll
        for (int j = 0; j < 8; j++) {
            uint32_t u01 = 0x64006400u | ((wa.x >> (4 * j)) & 0xFu)
                                       | (((wa.y >> (4 * j)) & 0xFu) << 16);
            uint32_t u23 = 0x64006400u | ((wa.z >> (4 * j)) & 0xFu)
                                       | (((wa.w >> (4 * j)) & 0xFu) << 16);
            uint32_t u45 = 0x64006400u | ((wb.x >> (4 * j)) & 0xFu)
                                       | (((wb.y >> (4 * j)) & 0xFu) << 16);
            uint32_t u67 = 0x64006400u | ((wb.z >> (4 * j)) & 0xFu)
                                       | (((wb.w >> (4 * j)) & 0xFu) << 16);
            __half2 h01 = __hmul2(__hsub2(*(__half2*)&u01, hz[0]), hs[0]);
            __half2 h23 = __hmul2(__hsub2(*(__half2*)&u23, hz[1]), hs[1]);
            __half2 h45 = __hmul2(__hsub2(*(__half2*)&u45, hz[2]), hs[2]);
            __half2 h67 = __hmul2(__hsub2(*(__half2*)&u67, hz[3]), hs[3]);
            uint4 v = make_uint4(*(uint32_t*)&h01, *(uint32_t*)&h23,
                                 *(uint32_t*)&h45, *(uint32_t*)&h67);
            *(uint4*)(dst + j * (B_LD * 2)) = v;
        }
    };

    // ---- prologue: stages 0,1 fully staged; regs/consts ready for stage 2 ----
    ldg_consts(0);                 // group of stages 0,1
    ldg_b(0);
    issue_a(0, sbase + 0 * STAGE_BYTES);
    CP_COMMIT();
    issue_a(1, sbase + 1 * STAGE_BYTES);
    CP_COMMIT();
    store_b(0 * STAGE_BYTES + A_STAGE_BYTES);
    ldg_b(1);
    store_b(1 * STAGE_BYTES + A_STAGE_BYTES);
    ldg_consts(1);                 // group of stages 2,3
    ldg_b(2);
    __syncthreads();

    for (int ks = 0; ks < NITER; ks++) {
        const int buf  = ks % NSTAGE;
        const int nbuf = (ks + 2) % NSTAGE;

        // ---- produce stage ks+2 (data/consts prefetched at ks-1) ----
        if (ks + 2 < NITER)
            issue_a(ks + 2, sbase + nbuf * STAGE_BYTES);
        CP_COMMIT();                          // commit every iter (may be empty)
        if (ks + 2 < NITER)
            store_b((uint32_t)(nbuf * STAGE_BYTES + A_STAGE_BYTES));
        if (ks + 3 < NITER) {
            if (ks & 1)
                ldg_consts((ks + 3) >> 1);    // group boundary ahead
            ldg_b(ks + 3);
        }

        CP_WAIT2();                           // group ks committed 2 iters ago

        // ---- compute stage ks ----
        const __half* As = (const __half*)(smem + buf * STAGE_BYTES);
        const __half* Bs = (const __half*)(smem + buf * STAGE_BYTES + A_STAGE_BYTES);
        #pragma unroll
        for (int kk = 0; kk < BK; kk += 16) {
            wmma::fragment<wmma::matrix_a, 16, 16, 16, __half, wmma::row_major> af[4];
            #pragma unroll
            for (int i = 0; i < 4; i++)
                wmma::load_matrix_sync(af[i], As + (wm + i * 16) * A_LD + kk, A_LD);
            #pragma unroll
            for (int j = 0; j < 4; j++) {
                wmma::fragment<wmma::matrix_b, 16, 16, 16, __half, wmma::row_major> bf;
                wmma::load_matrix_sync(bf, Bs + kk * B_LD + wn + j * 16, B_LD);
                #pragma unroll
                for (int i = 0; i < 4; i++)
                    wmma::mma_sync(acc[i][j], af[i], bf, acc[i][j]);
            }
        }

        __syncthreads();                      // STS visibility + buffer reuse
    }

    // ---- epilogue: stage fp32 per warp (16x64 chunks), add bias, write ----
    float* fbuf = (float*)(smem + STAGE_BYTES) + warp * 16 * C_LD;
    const float* brow = bias + bn + wn;
    #pragma unroll
    for (int i = 0; i < 4; i++) {
        #pragma unroll
        for (int j = 0; j < 4; j++)
            wmma::store_matrix_sync(fbuf + j * 16, acc[i][j], C_LD, wmma::mem_row_major);
        __syncwarp();
        #pragma unroll
        for (int ii = 0; ii < 8; ii++) {
            int idx4 = lane + 32 * ii;          // 256 float4 = 16x64
            int row  = idx4 >> 4;
            int col  = (idx4 & 15) * 4;
            float4 v = *(float4*)(fbuf + row * C_LD + col);
            float4 b4 = *(const float4*)(brow + col);
            v.x += b4.x; v.y += b4.y; v.z += b4.z; v.w += b4.w;
            *(float4*)(out + (size_t)(bm + wm + i * 16 + row) * N_OUT + bn + wn + col) = v;
        }
        __syncwarp();
    }
}

// ---------------------------------------------------------------------------
// Launch.  Inputs: x(f32), qweight(i32), qzeros(i32), scales(f32), g_idx(i32),
//                  bias(f32).  Output f32 [M_TOK, N_OUT].
// ---------------------------------------------------------------------------
extern "C" void kernel_launch(void* const* d_in, const int* in_sizes, int n_in,
                              void* d_out, int out_size)
{
    const float* x       = (const float*)d_in[0];
    const int*   qweight = (const int*)d_in[1];
    const int*   qzeros  = (const int*)d_in[2];
    const float* scales  = (const float*)d_in[3];
    const float* bias    = (const float*)d_in[5];
    float* out = (float*)d_out;

    {
        size_t n4 = (size_t)M_TOK * K_IN / 4;
        convert_x_kernel<<<(unsigned)((n4 + 255) / 256), 256>>>(x);
    }
    {
        cudaFuncSetAttribute(gemm_q4_kernel,
                             cudaFuncAttributeMaxDynamicSharedMemorySize,
                             SMEM_DYN);
        dim3 grid(M_TOK / BM, N_OUT / BN);   // (32, 86), M fastest
        gemm_q4_kernel<<<grid, NTHREADS, SMEM_DYN>>>(qweight, qzeros, scales, bias, out);
    }
}